// round 1
// baseline (speedup 1.0000x reference)
#include <cuda_runtime.h>
#include <cuda_bf16.h>

#define N_NODES 100000
#define N_EDGES 1600000
#define TOT (N_EDGES + N_NODES)   // 1,700,000 entries incl. self loops
#define NB_SCAN ((N_NODES + 1023) / 1024)   // 98 blocks

// ---------------- scratch (static device globals; no allocs allowed) ----------
__device__ int   g_deg[N_NODES];
__device__ int   g_incl[N_NODES];
__device__ int   g_bsum[128];
__device__ int   g_boff[128];
__device__ int   g_rowptr[N_NODES + 1];
__device__ int   g_cursor[N_NODES];
__device__ int   g_col[TOT];
__device__ float g_dinv[N_NODES];
__device__ int   g_is64;

__device__ float g_G[N_NODES * 64];   // GEMM output (dinv-prescaled messages)
__device__ float g_H[N_NODES * 64];   // hidden activations
__device__ float g_XT[N_NODES * 64];  // x_temp (residual)

// ---------------- edge-index dtype detection (int64 vs silently-int32) --------
__global__ void k_detect(const void* ei) {
    if (threadIdx.x == 0 && blockIdx.x == 0) {
        const long long* p = (const long long*)ei;
        int ok64 = 1;
        #pragma unroll
        for (int i = 0; i < 16; i++) {
            long long v = p[i];
            if (v < 0 || v >= N_NODES) ok64 = 0;
        }
        g_is64 = ok64;
    }
}

__device__ __forceinline__ int load_idx(const void* ei, int pos) {
    if (g_is64) return (int)((const long long*)ei)[pos];
    return ((const int*)ei)[pos];
}

// ---------------- CSR build ---------------------------------------------------
__global__ void k_initdeg() {
    int i = blockIdx.x * blockDim.x + threadIdx.x;
    if (i < N_NODES) g_deg[i] = 1;   // self loop
}

__global__ void k_count(const void* ei) {
    int t = blockIdx.x * blockDim.x + threadIdx.x;
    if (t < N_EDGES) {
        int d = load_idx(ei, N_EDGES + t);
        atomicAdd(&g_deg[d], 1);
    }
}

__global__ void k_scan1() {
    __shared__ int s[1024];
    int tid = threadIdx.x;
    int i = blockIdx.x * 1024 + tid;
    int v = (i < N_NODES) ? g_deg[i] : 0;
    s[tid] = v;
    __syncthreads();
    #pragma unroll
    for (int off = 1; off < 1024; off <<= 1) {
        int t = (tid >= off) ? s[tid - off] : 0;
        __syncthreads();
        s[tid] += t;
        __syncthreads();
    }
    if (i < N_NODES) g_incl[i] = s[tid];
    if (tid == 1023) g_bsum[blockIdx.x] = s[1023];
}

__global__ void k_scan2() {
    __shared__ int s[128];
    int tid = threadIdx.x;
    int v = (tid < NB_SCAN) ? g_bsum[tid] : 0;
    s[tid] = v;
    __syncthreads();
    #pragma unroll
    for (int off = 1; off < 128; off <<= 1) {
        int t = (tid >= off) ? s[tid - off] : 0;
        __syncthreads();
        s[tid] += t;
        __syncthreads();
    }
    g_boff[tid] = s[tid] - v;   // exclusive
}

__global__ void k_finalize() {
    int i = blockIdx.x * blockDim.x + threadIdx.x;
    if (i < N_NODES) {
        int rp = g_incl[i] - g_deg[i] + g_boff[i >> 10];
        g_rowptr[i] = rp;
        g_cursor[i] = rp;
        g_dinv[i]   = rsqrtf((float)g_deg[i]);
    }
    if (i == 0) g_rowptr[N_NODES] = TOT;
}

__global__ void k_fill(const void* ei) {
    int t = blockIdx.x * blockDim.x + threadIdx.x;
    if (t < N_EDGES) {
        int s = load_idx(ei, t);
        int d = load_idx(ei, N_EDGES + t);
        int pos = atomicAdd(&g_cursor[d], 1);
        g_col[pos] = s;
    } else if (t < TOT) {
        int i = t - N_EDGES;
        int pos = atomicAdd(&g_cursor[i], 1);
        g_col[pos] = i;
    }
}

// ---------------- dense transform: G[row] = dinv[row] * (H[row] @ W) ----------
// warp-per-row, W staged in smem, shfl broadcast of the row values.
template <int K>
__global__ void k_gemm(const float* __restrict__ H, const float* __restrict__ W,
                       float* __restrict__ G) {
    __shared__ float sW[K * 64];
    for (int idx = threadIdx.x; idx < K * 64; idx += blockDim.x) sW[idx] = W[idx];
    __syncthreads();

    int lane   = threadIdx.x & 31;
    int warp   = (blockIdx.x * blockDim.x + threadIdx.x) >> 5;
    int nwarps = (gridDim.x * blockDim.x) >> 5;

    for (int row = warp; row < N_NODES; row += nwarps) {
        const float* hrow = H + (size_t)row * K;
        float ax = 0.f, ay = 0.f;
        #pragma unroll
        for (int k0 = 0; k0 < K; k0 += 32) {
            float hv = hrow[k0 + lane];
            #pragma unroll
            for (int kk = 0; kk < 32; kk++) {
                float a = __shfl_sync(0xffffffffu, hv, kk);
                float2 w = *(const float2*)&sW[(k0 + kk) * 64 + lane * 2];
                ax = fmaf(a, w.x, ax);
                ay = fmaf(a, w.y, ay);
            }
        }
        float di = g_dinv[row];
        *(float2*)&G[(size_t)row * 64 + lane * 2] = make_float2(ax * di, ay * di);
    }
}

// ---------------- aggregation: out[i] = f(dinv[i]*sum_{j in row} G[col[j]] + b)
// warp-per-node gather (L2-resident G), 4x edge unroll for MLP.
template <bool RELU, bool ADDRES>
__global__ void k_agg(const float* __restrict__ G, const float* __restrict__ bias,
                      const float* __restrict__ res, float* __restrict__ out) {
    int lane = threadIdx.x & 31;
    int row  = (blockIdx.x * blockDim.x + threadIdx.x) >> 5;
    if (row >= N_NODES) return;

    int start = g_rowptr[row];
    int end   = g_rowptr[row + 1];
    float ax = 0.f, ay = 0.f;
    int e = start;
    for (; e + 4 <= end; e += 4) {
        int c0 = g_col[e], c1 = g_col[e + 1], c2 = g_col[e + 2], c3 = g_col[e + 3];
        float2 v0 = *(const float2*)&G[(size_t)c0 * 64 + lane * 2];
        float2 v1 = *(const float2*)&G[(size_t)c1 * 64 + lane * 2];
        float2 v2 = *(const float2*)&G[(size_t)c2 * 64 + lane * 2];
        float2 v3 = *(const float2*)&G[(size_t)c3 * 64 + lane * 2];
        ax += (v0.x + v1.x) + (v2.x + v3.x);
        ay += (v0.y + v1.y) + (v2.y + v3.y);
    }
    for (; e < end; ++e) {
        int c = g_col[e];
        float2 v = *(const float2*)&G[(size_t)c * 64 + lane * 2];
        ax += v.x;
        ay += v.y;
    }
    float di = g_dinv[row];
    float2 b = *(const float2*)&bias[lane * 2];
    float ox = ax * di + b.x;
    float oy = ay * di + b.y;
    if (RELU) { ox = fmaxf(ox, 0.f); oy = fmaxf(oy, 0.f); }
    if (ADDRES) {
        float2 r = *(const float2*)&res[(size_t)row * 64 + lane * 2];
        ox += r.x; oy += r.y;
    }
    *(float2*)&out[(size_t)row * 64 + lane * 2] = make_float2(ox, oy);
}

// ---------------- launch -------------------------------------------------------
extern "C" void kernel_launch(void* const* d_in, const int* in_sizes, int n_in,
                              void* d_out, int out_size) {
    const float* x  = (const float*)d_in[0];
    const void*  ei = d_in[1];                  // int64 (or silently int32)
    const float* W0 = (const float*)d_in[2];
    const float* b0 = (const float*)d_in[3];
    const float* Ws = (const float*)d_in[4];    // [2,64,64]
    const float* bs = (const float*)d_in[5];    // [2,64]
    float* out = (float*)d_out;

    const float* Ws0 = Ws;
    const float* Ws1 = Ws + 64 * 64;
    const float* bs0 = bs;
    const float* bs1 = bs + 64;

    float *G = nullptr, *H = nullptr, *XT = nullptr;
    cudaGetSymbolAddress((void**)&G,  g_G);
    cudaGetSymbolAddress((void**)&H,  g_H);
    cudaGetSymbolAddress((void**)&XT, g_XT);

    // ---- graph build (CSR over A + I, symmetric norm) ----
    k_detect<<<1, 32>>>(ei);
    k_initdeg<<<(N_NODES + 255) / 256, 256>>>();
    k_count<<<(N_EDGES + 255) / 256, 256>>>(ei);
    k_scan1<<<NB_SCAN, 1024>>>();
    k_scan2<<<1, 128>>>();
    k_finalize<<<(N_NODES + 255) / 256, 256>>>();
    k_fill<<<(TOT + 255) / 256, 256>>>(ei);

    const int GEMM_BLOCKS = 296;   // 2 * 148 SMs, grid-stride warps
    const int AGG_BLOCKS  = (N_NODES * 32 + 255) / 256;

    // ---- layer 0: x_temp = conv(x, W0, b0) ----
    k_gemm<128><<<GEMM_BLOCKS, 1024>>>(x, W0, G);
    k_agg<false, false><<<AGG_BLOCKS, 256>>>(G, b0, nullptr, XT);

    // ---- layer 1: h = relu(conv(x_temp, Ws0, bs0)) ----
    k_gemm<64><<<GEMM_BLOCKS, 1024>>>(XT, Ws0, G);
    k_agg<true, false><<<AGG_BLOCKS, 256>>>(G, bs0, nullptr, H);

    // ---- layer 2: out = relu(conv(h, Ws1, bs1)) + x_temp ----
    k_gemm<64><<<GEMM_BLOCKS, 1024>>>(H, Ws1, G);
    k_agg<true, true><<<AGG_BLOCKS, 256>>>(G, bs1, XT, out);
}

// round 2
// speedup vs baseline: 1.3453x; 1.3453x over previous
#include <cuda_runtime.h>
#include <cuda_bf16.h>

#define N_NODES 100000
#define N_EDGES 1600000
#define TOT (N_EDGES + N_NODES)
#define NB_SCAN ((N_NODES + 1023) / 1024)   // 98

// ---------------- scratch -----------------------------------------------------
__device__ int   g_deg[N_NODES];
__device__ int   g_incl[N_NODES];
__device__ int   g_bsum[128];
__device__ int   g_rowptr[N_NODES + 1];
__device__ int   g_cursor[N_NODES];
__device__ int   g_col[TOT];
__device__ float g_dinv[N_NODES];
__device__ int   g_is64;

__device__ float g_G[N_NODES * 64];   // message buffer A
__device__ float g_H[N_NODES * 64];   // message buffer B (ping-pong)
__device__ float g_XT[N_NODES * 64];  // x_temp residual

// ---------------- helpers ------------------------------------------------------
__device__ __forceinline__ int load_idx(const void* ei, int pos) {
    if (g_is64) return (int)((const long long*)ei)[pos];
    return ((const int*)ei)[pos];
}

// init deg=1 (self loop) + edge dtype detect (int64 vs silently-int32)
__global__ void k_init(const void* ei) {
    int i = blockIdx.x * blockDim.x + threadIdx.x;
    if (i < N_NODES) g_deg[i] = 1;
    if (i == 0) {
        const long long* p = (const long long*)ei;
        int ok64 = 1;
        #pragma unroll
        for (int j = 0; j < 16; j++) {
            long long v = p[j];
            if (v < 0 || v >= N_NODES) ok64 = 0;
        }
        g_is64 = ok64;
    }
}

__global__ void k_count(const void* ei) {
    int t = blockIdx.x * blockDim.x + threadIdx.x;
    if (t < N_EDGES) atomicAdd(&g_deg[load_idx(ei, N_EDGES + t)], 1);
}

__global__ void k_scan1() {
    __shared__ int s[1024];
    int tid = threadIdx.x;
    int i = blockIdx.x * 1024 + tid;
    int v = (i < N_NODES) ? g_deg[i] : 0;
    s[tid] = v;
    __syncthreads();
    #pragma unroll
    for (int off = 1; off < 1024; off <<= 1) {
        int t = (tid >= off) ? s[tid - off] : 0;
        __syncthreads();
        s[tid] += t;
        __syncthreads();
    }
    if (i < N_NODES) g_incl[i] = s[tid];
    if (tid == 1023) g_bsum[blockIdx.x] = s[1023];
}

// per-block serial prefix over the 98 block sums + finalize rowptr/cursor/dinv
__global__ void k_scan2f() {
    __shared__ int sb[128];
    int tid = threadIdx.x;
    if (tid < 128) sb[tid] = (tid < NB_SCAN) ? g_bsum[tid] : 0;
    __syncthreads();
    int boff = 0;
    for (int j = 0; j < (int)blockIdx.x; j++) boff += sb[j];
    int i = blockIdx.x * 1024 + tid;
    if (i < N_NODES) {
        int rp = g_incl[i] - g_deg[i] + boff;
        g_rowptr[i] = rp;
        g_cursor[i] = rp;
        g_dinv[i]   = rsqrtf((float)g_deg[i]);
    }
    if (i == 0) g_rowptr[N_NODES] = TOT;
}

__global__ void k_fill(const void* ei) {
    int t = blockIdx.x * blockDim.x + threadIdx.x;
    if (t < N_EDGES) {
        int s = load_idx(ei, t);
        int d = load_idx(ei, N_EDGES + t);
        g_col[atomicAdd(&g_cursor[d], 1)] = s;
    } else if (t < TOT) {
        int i = t - N_EDGES;
        g_col[atomicAdd(&g_cursor[i], 1)] = i;
    }
}

// ---------------- layer-0 GEMM: G = dinv * (x @ W0), tiled, no shfl -----------
// M-tile 128, N=64 full, K=128 in 4 chunks of 32. 256 threads, 4x8 per thread.
__global__ void __launch_bounds__(256) k_gemm0(const float* __restrict__ X,
                                               const float* __restrict__ W,
                                               float* __restrict__ G) {
    __shared__ float As[32][132];   // transposed: As[k][row]
    __shared__ float Bs[32][64];
    int tid = threadIdx.x;
    int block_row = blockIdx.x * 128;
    int txc = tid & 7;          // col group: cols txc*8 .. +7
    int tyr = tid >> 3;         // row group: rows tyr*4 .. +3

    int lrow = tid >> 1;                 // 0..127 (A staging)
    int kh   = (tid & 1) * 16;
    int lkB  = tid >> 3;                 // 0..31 (B staging)
    int lcB  = (tid & 7) * 8;

    float acc[4][8];
    #pragma unroll
    for (int i = 0; i < 4; i++)
        #pragma unroll
        for (int j = 0; j < 8; j++) acc[i][j] = 0.f;

    for (int k0 = 0; k0 < 128; k0 += 32) {
        // stage A transposed
        int grow = block_row + lrow;
        #pragma unroll
        for (int j = 0; j < 4; j++) {
            int ko = kh + j * 4;
            float4 v = make_float4(0.f, 0.f, 0.f, 0.f);
            if (grow < N_NODES) v = *(const float4*)&X[(size_t)grow * 128 + k0 + ko];
            As[ko + 0][lrow] = v.x;
            As[ko + 1][lrow] = v.y;
            As[ko + 2][lrow] = v.z;
            As[ko + 3][lrow] = v.w;
        }
        // stage B
        *(float4*)&Bs[lkB][lcB]     = *(const float4*)&W[(size_t)(k0 + lkB) * 64 + lcB];
        *(float4*)&Bs[lkB][lcB + 4] = *(const float4*)&W[(size_t)(k0 + lkB) * 64 + lcB + 4];
        __syncthreads();

        #pragma unroll 8
        for (int kk = 0; kk < 32; kk++) {
            float4 a  = *(const float4*)&As[kk][tyr * 4];
            float4 b0 = *(const float4*)&Bs[kk][txc * 8];
            float4 b1 = *(const float4*)&Bs[kk][txc * 8 + 4];
            float av[4] = {a.x, a.y, a.z, a.w};
            float bv[8] = {b0.x, b0.y, b0.z, b0.w, b1.x, b1.y, b1.z, b1.w};
            #pragma unroll
            for (int i = 0; i < 4; i++)
                #pragma unroll
                for (int j = 0; j < 8; j++)
                    acc[i][j] = fmaf(av[i], bv[j], acc[i][j]);
        }
        __syncthreads();
    }

    #pragma unroll
    for (int i = 0; i < 4; i++) {
        int gr = block_row + tyr * 4 + i;
        if (gr < N_NODES) {
            float di = g_dinv[gr];
            float4 o0 = make_float4(acc[i][0] * di, acc[i][1] * di, acc[i][2] * di, acc[i][3] * di);
            float4 o1 = make_float4(acc[i][4] * di, acc[i][5] * di, acc[i][6] * di, acc[i][7] * di);
            *(float4*)&G[(size_t)gr * 64 + txc * 8]     = o0;
            *(float4*)&G[(size_t)gr * 64 + txc * 8 + 4] = o1;
        }
    }
}

// ---------------- fused aggregate (+bias/relu/res) [+ next-layer GEMM] --------
// warp-per-node gather; epilogue GEMM via per-warp smem row broadcast (no shfl).
template <bool RELU, bool ADDRES, bool STORE_OUT, bool NEXT>
__global__ void __launch_bounds__(512) k_aggf(const float* __restrict__ G,
                                              const float* __restrict__ bias,
                                              const float* __restrict__ Wn,
                                              float* __restrict__ outp,
                                              const float* __restrict__ res,
                                              float* __restrict__ Gnext) {
    __shared__ float sW[64 * 64];
    __shared__ float sT[16][64];
    if (NEXT) {
        for (int idx = threadIdx.x; idx < 64 * 64; idx += 512) sW[idx] = Wn[idx];
    }
    __syncthreads();

    int lane = threadIdx.x & 31;
    int wid  = threadIdx.x >> 5;
    int node = blockIdx.x * 16 + wid;
    int nw   = gridDim.x * 16;
    float2 b = *(const float2*)&bias[lane * 2];

    for (int row = node; row < N_NODES; row += nw) {
        int s  = g_rowptr[row];
        int en = g_rowptr[row + 1];
        float ax = 0.f, ay = 0.f;
        int e = s;
        for (; e + 4 <= en; e += 4) {
            int c0 = g_col[e], c1 = g_col[e + 1], c2 = g_col[e + 2], c3 = g_col[e + 3];
            float2 v0 = *(const float2*)&G[(size_t)c0 * 64 + lane * 2];
            float2 v1 = *(const float2*)&G[(size_t)c1 * 64 + lane * 2];
            float2 v2 = *(const float2*)&G[(size_t)c2 * 64 + lane * 2];
            float2 v3 = *(const float2*)&G[(size_t)c3 * 64 + lane * 2];
            ax += (v0.x + v1.x) + (v2.x + v3.x);
            ay += (v0.y + v1.y) + (v2.y + v3.y);
        }
        for (; e < en; ++e) {
            int c = g_col[e];
            float2 v = *(const float2*)&G[(size_t)c * 64 + lane * 2];
            ax += v.x; ay += v.y;
        }
        float di = g_dinv[row];
        float ox = fmaf(ax, di, b.x);
        float oy = fmaf(ay, di, b.y);
        if (RELU) { ox = fmaxf(ox, 0.f); oy = fmaxf(oy, 0.f); }
        if (ADDRES) {
            float2 r = *(const float2*)&res[(size_t)row * 64 + lane * 2];
            ox += r.x; oy += r.y;
        }
        if (STORE_OUT)
            *(float2*)&outp[(size_t)row * 64 + lane * 2] = make_float2(ox, oy);
        if (NEXT) {
            *(float2*)&sT[wid][lane * 2] = make_float2(ox, oy);
            __syncwarp();
            float gx = 0.f, gy = 0.f;
            #pragma unroll 16
            for (int k = 0; k < 64; k++) {
                float a   = sT[wid][k];
                float2 w = *(const float2*)&sW[k * 64 + lane * 2];
                gx = fmaf(a, w.x, gx);
                gy = fmaf(a, w.y, gy);
            }
            *(float2*)&Gnext[(size_t)row * 64 + lane * 2] = make_float2(gx * di, gy * di);
            __syncwarp();
        }
    }
}

// ---------------- launch --------------------------------------------------------
extern "C" void kernel_launch(void* const* d_in, const int* in_sizes, int n_in,
                              void* d_out, int out_size) {
    const float* x  = (const float*)d_in[0];
    const void*  ei = d_in[1];
    const float* W0 = (const float*)d_in[2];
    const float* b0 = (const float*)d_in[3];
    const float* Ws = (const float*)d_in[4];
    const float* bs = (const float*)d_in[5];
    float* out = (float*)d_out;

    const float* Ws0 = Ws;
    const float* Ws1 = Ws + 64 * 64;
    const float* bs0 = bs;
    const float* bs1 = bs + 64;

    float *G = nullptr, *H = nullptr, *XT = nullptr;
    cudaGetSymbolAddress((void**)&G,  g_G);
    cudaGetSymbolAddress((void**)&H,  g_H);
    cudaGetSymbolAddress((void**)&XT, g_XT);

    // ---- CSR build ----
    k_init<<<(N_NODES + 255) / 256, 256>>>(ei);
    k_count<<<(N_EDGES + 511) / 512, 512>>>(ei);
    k_scan1<<<NB_SCAN, 1024>>>();
    k_scan2f<<<NB_SCAN, 1024>>>();
    k_fill<<<(TOT + 511) / 512, 512>>>(ei);

    const int GEMM0_BLOCKS = (N_NODES + 127) / 128;   // 782
    const int AGG_BLOCKS   = 592;                     // 4 blocks/SM x 148

    // layer 0 GEMM: G = dinv * (x @ W0)
    k_gemm0<<<GEMM0_BLOCKS, 256>>>(x, W0, G);
    // layer 0 agg -> XT; fused next GEMM: H = dinv * (XT @ Ws0)
    k_aggf<false, false, true, true><<<AGG_BLOCKS, 512>>>(G, b0, Ws0, XT, nullptr, H);
    // layer 1 agg (relu, h1 not materialized); fused: G = dinv * (h1 @ Ws1)
    k_aggf<true, false, false, true><<<AGG_BLOCKS, 512>>>(H, bs0, Ws1, nullptr, nullptr, G);
    // layer 2 agg (relu) + residual -> out
    k_aggf<true, true, true, false><<<AGG_BLOCKS, 512>>>(G, bs1, nullptr, out, XT, nullptr);
}